// round 11
// baseline (speedup 1.0000x reference)
#include <cuda_runtime.h>
#include <cuda_fp16.h>
#include <math_constants.h>

#define B    32
#define C    256
#define HW   4096          // 64*64
#define HID  16

// scratch (__device__ globals; allocation-free rule)
__device__ __half2 g_x16[B*C*HW/2];      // 67 MB fp16 shadow of x
__device__ float   g_avg [B*C];
__device__ float   g_max [B*C];
__device__ float   g_catt[B*C];
__device__ float   g_spavg[B*HW];
__device__ float   g_spmax[B*HW];

__device__ __forceinline__ float sigmoidf(float v) { return 1.f / (1.f + __expf(-v)); }

// ---------------------------------------------------------------------------
// k1: channel mean/max (exact fp32) + write fp16 shadow. 8192 blocks x 256.
// ---------------------------------------------------------------------------
__global__ __launch_bounds__(256) void k1_stats_cvt(const float* __restrict__ x) {
    int plane = blockIdx.x;                     // b*C + c
    const float4* xp = (const float4*)x + (size_t)plane * 1024;
    uint2* sh = (uint2*)g_x16 + (size_t)plane * 1024;

    float s = 0.f, m = -CUDART_INF_F;
#pragma unroll
    for (int k = 0; k < 4; k++) {
        int i = k * 256 + threadIdx.x;
        float4 v = __ldcs(&xp[i]);
        s += (v.x + v.y) + (v.z + v.w);
        m = fmaxf(m, fmaxf(fmaxf(v.x, v.y), fmaxf(v.z, v.w)));
        __half2 h01 = __floats2half2_rn(v.x, v.y);
        __half2 h23 = __floats2half2_rn(v.z, v.w);
        uint2 u;
        u.x = *(unsigned*)&h01;
        u.y = *(unsigned*)&h23;
        sh[i] = u;
    }
#pragma unroll
    for (int off = 16; off; off >>= 1) {
        s += __shfl_down_sync(0xffffffffu, s, off);
        m = fmaxf(m, __shfl_down_sync(0xffffffffu, m, off));
    }
    __shared__ float ss[8], sm[8];
    if ((threadIdx.x & 31) == 0) { ss[threadIdx.x >> 5] = s; sm[threadIdx.x >> 5] = m; }
    __syncthreads();
    if (threadIdx.x == 0) {
        float S = 0.f, M = -CUDART_INF_F;
#pragma unroll
        for (int i = 0; i < 8; i++) { S += ss[i]; M = fmaxf(M, sm[i]); }
        g_avg[plane] = S * (1.f / 4096.f);
        g_max[plane] = M;
    }
}

// ---------------------------------------------------------------------------
// k2: channel MLP + sigmoid -> g_catt. 32 blocks x 256 thr.
// ---------------------------------------------------------------------------
__global__ __launch_bounds__(256) void k2_mlp(const float* __restrict__ w1,
                                              const float* __restrict__ w2) {
    int b   = blockIdx.x;
    int tid = threadIdx.x;
    __shared__ float s_avg[C], s_mx[C], s_h[HID];
    s_avg[tid] = g_avg[b * C + tid];
    s_mx [tid] = g_max[b * C + tid];
    __syncthreads();

    int r = tid >> 4, l16 = tid & 15;
    float pa = 0.f, pm = 0.f;
#pragma unroll
    for (int j = 0; j < 16; j++) {
        int c = l16 + j * 16;
        float w = w1[r * C + c];
        pa += w * s_avg[c];
        pm += w * s_mx[c];
    }
#pragma unroll
    for (int off = 8; off; off >>= 1) {
        pa += __shfl_down_sync(0xffffffffu, pa, off, 16);
        pm += __shfl_down_sync(0xffffffffu, pm, off, 16);
    }
    if (l16 == 0) s_h[r] = fmaxf(pa, 0.f) + fmaxf(pm, 0.f);
    __syncthreads();

    float acc = 0.f;
#pragma unroll
    for (int rr = 0; rr < HID; rr++) acc += s_h[rr] * w2[tid * HID + rr];
    g_catt[b * C + tid] = sigmoidf(acc);
}

// ---------------------------------------------------------------------------
// k3: spatial mean/max of x16*catt. 1024 blocks x 256 thr. (R8 shape, 15us)
// ---------------------------------------------------------------------------
__global__ __launch_bounds__(256) void k3_spstats() {
    const int b   = blockIdx.x >> 5;
    const int g   = blockIdx.x & 31;            // 32 groups of 128 px
    const int tid = threadIdx.x;

    __shared__ float sc[C];
    sc[tid] = __ldg(&g_catt[b * C + tid]);
    __syncthreads();

    const int u4    = tid & 15;
    const int split = tid >> 4;             // 16 channels each
    const uint4* xp = (const uint4*)g_x16 + (size_t)(b * C) * 512 + g * 16 + u4;

    float s[8], m[8];
#pragma unroll
    for (int i = 0; i < 8; i++) { s[i] = 0.f; m[i] = -CUDART_INF_F; }

#pragma unroll
    for (int half = 0; half < 2; half++) {
        uint4 u[8];
#pragma unroll
        for (int j = 0; j < 8; j++)
            u[j] = xp[(size_t)(split * 16 + half * 8 + j) * 512];
#pragma unroll
        for (int j = 0; j < 8; j++) {
            float a = sc[split * 16 + half * 8 + j];
            float2 f01 = __half22float2(*(__half2*)&u[j].x);
            float2 f23 = __half22float2(*(__half2*)&u[j].y);
            float2 f45 = __half22float2(*(__half2*)&u[j].z);
            float2 f67 = __half22float2(*(__half2*)&u[j].w);
            float v[8] = {f01.x, f01.y, f23.x, f23.y, f45.x, f45.y, f67.x, f67.y};
#pragma unroll
            for (int i = 0; i < 8; i++) {
                float t = v[i] * a;
                s[i] += t;
                m[i] = fmaxf(m[i], t);
            }
        }
    }

    __shared__ float rsum[16][16][8];
    __shared__ float rmax[16][16][8];
#pragma unroll
    for (int i = 0; i < 8; i++) { rsum[split][u4][i] = s[i]; rmax[split][u4][i] = m[i]; }
    __syncthreads();

    if (tid < 128) {
        int p = tid >> 3, lane = tid & 7;
        float S = rsum[0][p][lane], M = rmax[0][p][lane];
#pragma unroll
        for (int i = 1; i < 16; i++) {
            S += rsum[i][p][lane];
            M = fmaxf(M, rmax[i][p][lane]);
        }
        int pix = g * 128 + p * 8 + lane;
        g_spavg[b * HW + pix] = S * (1.f / (float)C);
        g_spmax[b * HW + pix] = M;
    }
}

// ---------------------------------------------------------------------------
// k45: FUSED redundant conv + apply. 2048 blocks x 256 thr.
// Block = (batch, 8-row band, 32-channel group). Conv recomputed 8x per band
// (amortized over 96KB of apply traffic; kills the k4 launch entirely).
// ---------------------------------------------------------------------------
__global__ __launch_bounds__(256) void k45_fused(const float* __restrict__ w_sp,
                                                 float* __restrict__ out) {
    const int b    = blockIdx.x >> 6;
    const int rest = blockIdx.x & 63;
    const int band = rest >> 3;             // 0..7 -> 8 rows each
    const int cg   = rest & 7;              // 0..7 -> 32 channels each
    const int h0   = band * 8;
    const int tid  = threadIdx.x;

    __shared__ float sp[2][14 * 72];            // rows h0-3..h0+10, col pad 3
    __shared__ float s_w[98];
    __shared__ __align__(16) float s_att[512];  // 8x64 tile
    __shared__ float s_c[32];

    if (tid < 98) s_w[tid] = __ldg(&w_sp[tid]);
    if (tid < 32) s_c[tid] = __ldg(&g_catt[b * C + cg * 32 + tid]);

    // single predicated fill of the whole padded tile (2016 entries)
    for (int idx = tid; idx < 2 * 14 * 72; idx += 256) {
        int pl  = idx >= 1008;
        int rem = idx - pl * 1008;
        int r   = rem / 72;
        int cx  = rem - r * 72 - 3;
        int gh  = h0 + r - 3;
        float v = 0.f;
        if (gh >= 0 && gh < 64 && cx >= 0 && cx < 64)
            v = pl ? __ldg(&g_spmax[b * HW + gh * 64 + cx])
                   : __ldg(&g_spavg[b * HW + gh * 64 + cx]);
        ((float*)sp)[idx] = v;
    }
    __syncthreads();

    // conv: 512 tile pixels, 2 per thread
#pragma unroll
    for (int t2 = 0; t2 < 2; t2++) {
        int t  = tid + t2 * 256;
        int hl = t >> 6;
        int wx = t & 63;
        float acc = 0.f;
#pragma unroll
        for (int i = 0; i < 2; i++)
#pragma unroll
            for (int kh = 0; kh < 7; kh++) {
                const float* row  = &sp[i][(hl + kh) * 72 + wx];
                const float* wrow = &s_w[i * 49 + kh * 7];
#pragma unroll
                for (int kw = 0; kw < 7; kw++)
                    acc += row[kw] * wrow[kw];
            }
        s_att[t] = sigmoidf(acc);
    }
    __syncthreads();

    // apply: thread = (u4 0..63 within band, split 0..3 of 8 channels),
    // 2 batches of 4 prefetched loads.
    {
        const int u4    = tid & 63;
        const int split = tid >> 6;
        const float4* a4p = (const float4*)s_att + u4 * 2;
        const float4 aA = a4p[0], aB = a4p[1];

        const uint4* xbase = (const uint4*)g_x16
                           + (size_t)(b * C + cg * 32) * 512 + band * 64 + u4;
        float4* obase = (float4*)out
                      + (size_t)(b * C + cg * 32) * 1024 + band * 128 + u4 * 2;

#pragma unroll
        for (int half = 0; half < 2; half++) {
            uint4 u[4];
#pragma unroll
            for (int j = 0; j < 4; j++) {
                int ci = split * 8 + half * 4 + j;
                u[j] = __ldcs(&xbase[(size_t)ci * 512]);
            }
#pragma unroll
            for (int j = 0; j < 4; j++) {
                int ci   = split * 8 + half * 4 + j;
                float ca = s_c[ci];
                float2 f01 = __half22float2(*(__half2*)&u[j].x);
                float2 f23 = __half22float2(*(__half2*)&u[j].y);
                float2 f45 = __half22float2(*(__half2*)&u[j].z);
                float2 f67 = __half22float2(*(__half2*)&u[j].w);
                float4 oA, oB;
                oA.x = f01.x * ca * aA.x;
                oA.y = f01.y * ca * aA.y;
                oA.z = f23.x * ca * aA.z;
                oA.w = f23.y * ca * aA.w;
                oB.x = f45.x * ca * aB.x;
                oB.y = f45.y * ca * aB.y;
                oB.z = f67.x * ca * aB.z;
                oB.w = f67.y * ca * aB.w;
                __stcs(obase + (size_t)ci * 1024, oA);
                __stcs(obase + (size_t)ci * 1024 + 1, oB);
            }
        }
    }
}

// ---------------------------------------------------------------------------
extern "C" void kernel_launch(void* const* d_in, const int* in_sizes, int n_in,
                              void* d_out, int out_size) {
    const float* x    = (const float*)d_in[0];   // [32,256,64,64]
    const float* w1   = (const float*)d_in[1];   // [16,256]
    const float* w2   = (const float*)d_in[2];   // [256,16]
    const float* w_sp = (const float*)d_in[3];   // [1,2,7,7]
    float* out = (float*)d_out;

    k1_stats_cvt<<<B * C, 256>>>(x);
    k2_mlp      <<<B, 256>>>(w1, w2);
    k3_spstats  <<<B * 32, 256>>>();
    k45_fused   <<<B * 64, 256>>>(w_sp, out);
}

// round 12
// speedup vs baseline: 1.1708x; 1.1708x over previous
#include <cuda_runtime.h>
#include <cuda_fp16.h>
#include <math_constants.h>

#define B    32
#define C    256
#define HW   4096          // 64*64
#define HID  16

// scratch (__device__ globals; allocation-free rule)
__device__ __half2 g_x16[B*C*HW/2];      // 67 MB fp16 shadow of x
__device__ float   g_avg [B*C];
__device__ float   g_max [B*C];
__device__ float   g_catt[B*C];
__device__ float   g_spavg[B*HW];
__device__ float   g_spmax[B*HW];
__device__ float   g_att [B*HW];         // sigmoid(conv) result

__device__ __forceinline__ float sigmoidf(float v) { return 1.f / (1.f + __expf(-v)); }

#if defined(__CUDA_ARCH__) && (__CUDA_ARCH__ >= 900)
__device__ __forceinline__ void dep_sync() { cudaGridDependencySynchronize(); }
#else
__device__ __forceinline__ void dep_sync() {}
#endif

// ---------------------------------------------------------------------------
// k1: channel mean/max (exact fp32) + write fp16 shadow. 8192 blocks x 256.
// ---------------------------------------------------------------------------
__global__ __launch_bounds__(256) void k1_stats_cvt(const float* __restrict__ x) {
    int plane = blockIdx.x;                     // b*C + c
    const float4* xp = (const float4*)x + (size_t)plane * 1024;
    uint2* sh = (uint2*)g_x16 + (size_t)plane * 1024;

    float s = 0.f, m = -CUDART_INF_F;
#pragma unroll
    for (int k = 0; k < 4; k++) {
        int i = k * 256 + threadIdx.x;
        float4 v = __ldcs(&xp[i]);
        s += (v.x + v.y) + (v.z + v.w);
        m = fmaxf(m, fmaxf(fmaxf(v.x, v.y), fmaxf(v.z, v.w)));
        __half2 h01 = __floats2half2_rn(v.x, v.y);
        __half2 h23 = __floats2half2_rn(v.z, v.w);
        uint2 u;
        u.x = *(unsigned*)&h01;
        u.y = *(unsigned*)&h23;
        sh[i] = u;
    }
#pragma unroll
    for (int off = 16; off; off >>= 1) {
        s += __shfl_down_sync(0xffffffffu, s, off);
        m = fmaxf(m, __shfl_down_sync(0xffffffffu, m, off));
    }
    __shared__ float ss[8], sm[8];
    if ((threadIdx.x & 31) == 0) { ss[threadIdx.x >> 5] = s; sm[threadIdx.x >> 5] = m; }
    __syncthreads();
    if (threadIdx.x == 0) {
        float S = 0.f, M = -CUDART_INF_F;
#pragma unroll
        for (int i = 0; i < 8; i++) { S += ss[i]; M = fmaxf(M, sm[i]); }
        g_avg[plane] = S * (1.f / 4096.f);
        g_max[plane] = M;
    }
}

// ---------------------------------------------------------------------------
// k2: channel MLP + sigmoid -> g_catt. 32 blocks x 256 thr.
// ---------------------------------------------------------------------------
__global__ __launch_bounds__(256) void k2_mlp(const float* __restrict__ w1,
                                              const float* __restrict__ w2) {
    int b   = blockIdx.x;
    int tid = threadIdx.x;
    __shared__ float s_avg[C], s_mx[C], s_h[HID];
    dep_sync();                                 // wait for k1 stats
    s_avg[tid] = g_avg[b * C + tid];
    s_mx [tid] = g_max[b * C + tid];
    __syncthreads();

    int r = tid >> 4, l16 = tid & 15;
    float pa = 0.f, pm = 0.f;
#pragma unroll
    for (int j = 0; j < 16; j++) {
        int c = l16 + j * 16;
        float w = w1[r * C + c];
        pa += w * s_avg[c];
        pm += w * s_mx[c];
    }
#pragma unroll
    for (int off = 8; off; off >>= 1) {
        pa += __shfl_down_sync(0xffffffffu, pa, off, 16);
        pm += __shfl_down_sync(0xffffffffu, pm, off, 16);
    }
    if (l16 == 0) s_h[r] = fmaxf(pa, 0.f) + fmaxf(pm, 0.f);
    __syncthreads();

    float acc = 0.f;
#pragma unroll
    for (int rr = 0; rr < HID; rr++) acc += s_h[rr] * w2[tid * HID + rr];
    g_catt[b * C + tid] = sigmoidf(acc);
}

// ---------------------------------------------------------------------------
// k3: spatial mean/max of x16*catt. 1024 blocks x 256 thr. (94.3us config)
// ---------------------------------------------------------------------------
__global__ __launch_bounds__(256) void k3_spstats() {
    const int b   = blockIdx.x >> 5;
    const int g   = blockIdx.x & 31;            // 32 groups of 128 px
    const int tid = threadIdx.x;

    __shared__ float sc[C];
    dep_sync();                                 // wait for k2 catt
    sc[tid] = g_catt[b * C + tid];
    __syncthreads();

    const int u4    = tid & 15;
    const int split = tid >> 4;             // 16 channels each
    const uint4* xp = (const uint4*)g_x16 + (size_t)(b * C) * 512 + g * 16 + u4;

    float s[8], m[8];
#pragma unroll
    for (int i = 0; i < 8; i++) { s[i] = 0.f; m[i] = -CUDART_INF_F; }

#pragma unroll
    for (int j = 0; j < 16; j++) {
        int c   = split * 16 + j;
        float a = sc[c];
        uint4 u = xp[(size_t)c * 512];
        float2 f01 = __half22float2(*(__half2*)&u.x);
        float2 f23 = __half22float2(*(__half2*)&u.y);
        float2 f45 = __half22float2(*(__half2*)&u.z);
        float2 f67 = __half22float2(*(__half2*)&u.w);
        float v[8] = {f01.x, f01.y, f23.x, f23.y, f45.x, f45.y, f67.x, f67.y};
#pragma unroll
        for (int i = 0; i < 8; i++) {
            float t = v[i] * a;
            s[i] += t;
            m[i] = fmaxf(m[i], t);
        }
    }

    __shared__ float rsum[16][16][8];
    __shared__ float rmax[16][16][8];
#pragma unroll
    for (int i = 0; i < 8; i++) { rsum[split][u4][i] = s[i]; rmax[split][u4][i] = m[i]; }
    __syncthreads();

    if (tid < 128) {
        int p = tid >> 3, lane = tid & 7;
        float S = rsum[0][p][lane], M = rmax[0][p][lane];
#pragma unroll
        for (int i = 1; i < 16; i++) {
            S += rsum[i][p][lane];
            M = fmaxf(M, rmax[i][p][lane]);
        }
        int pix = g * 128 + p * 8 + lane;
        g_spavg[b * HW + pix] = S * (1.f / (float)C);
        g_spmax[b * HW + pix] = M;
    }
}

// ---------------------------------------------------------------------------
// k4: 7x7 "same" conv + sigmoid -> g_att. 512 blocks x 256 thr, 1 px/thread.
// Weight load + tile zeroing happen BEFORE dep_sync (overlaps k3 tail).
// ---------------------------------------------------------------------------
__global__ __launch_bounds__(256) void k4_conv(const float* __restrict__ w_sp) {
    const int b    = blockIdx.x >> 4;
    const int band = blockIdx.x & 15;
    const int h0   = band * 4;
    const int tid  = threadIdx.x;

    __shared__ float sp[2][10 * 72];            // rows h0-3..h0+6, col pad 3
    __shared__ float s_w[98];

    // pre-sync work: weights (kernel input, not produced by k3) + zero fill
    if (tid < 98) s_w[tid] = w_sp[tid];
    for (int i = tid; i < 2 * 10 * 72; i += 256) ((float*)sp)[i] = 0.f;

    dep_sync();                                 // wait for k3 spavg/spmax
    __syncthreads();

    for (int idx = tid; idx < 10 * 64; idx += 256) {
        int r  = idx >> 6;
        int cx = idx & 63;
        int gh = h0 + r - 3;
        if (gh >= 0 && gh < 64) {
            sp[0][r * 72 + 3 + cx] = g_spavg[b * HW + gh * 64 + cx];
            sp[1][r * 72 + 3 + cx] = g_spmax[b * HW + gh * 64 + cx];
        }
    }
    __syncthreads();

    int hl = tid >> 6;      // 0..3
    int wx = tid & 63;
    float acc = 0.f;
#pragma unroll
    for (int i = 0; i < 2; i++)
#pragma unroll
        for (int kh = 0; kh < 7; kh++) {
            const float* row  = &sp[i][(hl + kh) * 72 + wx];
            const float* wrow = &s_w[i * 49 + kh * 7];
#pragma unroll
            for (int kw = 0; kw < 7; kw++)
                acc += row[kw] * wrow[kw];
        }
    g_att[b * HW + (h0 + hl) * 64 + wx] = sigmoidf(acc);
}

// ---------------------------------------------------------------------------
// k5: pure apply: out = x16 * catt * att. 2048 blocks x 256 thr. (94.3us cfg)
// ---------------------------------------------------------------------------
__global__ __launch_bounds__(256) void k5_final(float* __restrict__ out) {
    const int b    = blockIdx.x >> 6;
    const int rest = blockIdx.x & 63;
    const int band = rest >> 3;             // 0..7 -> 8 rows each
    const int cg   = rest & 7;              // 0..7 -> 32 channels each
    const int tid  = threadIdx.x;

    __shared__ __align__(16) float s_att[512];
    __shared__ float s_c[32];

    dep_sync();                                 // wait for k4 att
    s_att[tid]       = g_att[b * HW + band * 512 + tid];
    s_att[tid + 256] = g_att[b * HW + band * 512 + tid + 256];
    if (tid < 32) s_c[tid] = g_catt[b * C + cg * 32 + tid];
    __syncthreads();

    const int u4    = tid & 63;             // 8 consecutive pixels in band
    const int split = tid >> 6;             // 0..3
    const float4* a4p = (const float4*)s_att + u4 * 2;
    float4 aA = a4p[0], aB = a4p[1];

    const uint4* xbase = (const uint4*)g_x16
                       + (size_t)(b * C + cg * 32) * 512 + band * 64 + u4;
    float4* obase = (float4*)out
                  + ((size_t)(b * C + cg * 32) * 1024) + band * 128 + u4 * 2;

#pragma unroll 4
    for (int j = 0; j < 8; j++) {
        int ci   = split * 8 + j;
        float ca = s_c[ci];
        uint4 u  = xbase[(size_t)ci * 512];
        float2 f01 = __half22float2(*(__half2*)&u.x);
        float2 f23 = __half22float2(*(__half2*)&u.y);
        float2 f45 = __half22float2(*(__half2*)&u.z);
        float2 f67 = __half22float2(*(__half2*)&u.w);
        float4 oA, oB;
        oA.x = f01.x * ca * aA.x;
        oA.y = f01.y * ca * aA.y;
        oA.z = f23.x * ca * aA.z;
        oA.w = f23.y * ca * aA.w;
        oB.x = f45.x * ca * aB.x;
        oB.y = f45.y * ca * aB.y;
        oB.z = f67.x * ca * aB.z;
        oB.w = f67.y * ca * aB.w;
        __stcs(obase + (size_t)ci * 1024, oA);
        __stcs(obase + (size_t)ci * 1024 + 1, oB);
    }
}

// ---------------------------------------------------------------------------
// host: PDL-chained launches with plain fallback
// ---------------------------------------------------------------------------
template <typename... Args>
static void launch_pdl(void (*kern)(Args...), dim3 grid, dim3 block, Args... args) {
    cudaLaunchConfig_t cfg = {};
    cfg.gridDim  = grid;
    cfg.blockDim = block;
    cfg.stream   = 0;
    cudaLaunchAttribute attr[1];
    attr[0].id = cudaLaunchAttributeProgrammaticStreamSerialization;
    attr[0].val.programmaticStreamSerializationAllowed = 1;
    cfg.attrs    = attr;
    cfg.numAttrs = 1;
    cudaError_t err = cudaLaunchKernelEx(&cfg, kern, args...);
    if (err != cudaSuccess) {
        cudaGetLastError();                     // clear, fall back
        kern<<<grid, block>>>(args...);
    }
}

extern "C" void kernel_launch(void* const* d_in, const int* in_sizes, int n_in,
                              void* d_out, int out_size) {
    const float* x    = (const float*)d_in[0];   // [32,256,64,64]
    const float* w1   = (const float*)d_in[1];   // [16,256]
    const float* w2   = (const float*)d_in[2];   // [256,16]
    const float* w_sp = (const float*)d_in[3];   // [1,2,7,7]
    float* out = (float*)d_out;

    k1_stats_cvt<<<B * C, 256>>>(x);
    launch_pdl(k2_mlp,     dim3(B),       dim3(256), w1, w2);
    launch_pdl(k3_spstats, dim3(B * 32),  dim3(256));
    launch_pdl(k4_conv,    dim3(B * 16),  dim3(256), w_sp);
    launch_pdl(k5_final,   dim3(B * 64),  dim3(256), out);
}

// round 13
// speedup vs baseline: 1.1720x; 1.0011x over previous
#include <cuda_runtime.h>
#include <cuda_fp16.h>
#include <math_constants.h>

#define B    32
#define C    256
#define HW   4096          // 64*64
#define HID  16

// scratch (__device__ globals; allocation-free rule)
__device__ __half2 g_x16[B*C*HW/2];      // 67 MB fp16 shadow of x
__device__ float   g_avg [B*C];
__device__ float   g_max [B*C];
__device__ float   g_catt[B*C];
__device__ float   g_spavg[B*HW];
__device__ float   g_spmax[B*HW];
__device__ __align__(16) float g_att[B*HW];   // sigmoid(conv) result

__device__ __forceinline__ float sigmoidf(float v) { return 1.f / (1.f + __expf(-v)); }

#if defined(__CUDA_ARCH__) && (__CUDA_ARCH__ >= 900)
__device__ __forceinline__ void dep_sync() { cudaGridDependencySynchronize(); }
#else
__device__ __forceinline__ void dep_sync() {}
#endif

// ---------------------------------------------------------------------------
// k1: channel mean/max (exact fp32) + write fp16 shadow. 8192 blocks x 256.
// ---------------------------------------------------------------------------
__global__ __launch_bounds__(256) void k1_stats_cvt(const float* __restrict__ x) {
    int plane = blockIdx.x;                     // b*C + c
    const float4* xp = (const float4*)x + (size_t)plane * 1024;
    uint2* sh = (uint2*)g_x16 + (size_t)plane * 1024;

    float s = 0.f, m = -CUDART_INF_F;
#pragma unroll
    for (int k = 0; k < 4; k++) {
        int i = k * 256 + threadIdx.x;
        float4 v = __ldcs(&xp[i]);
        s += (v.x + v.y) + (v.z + v.w);
        m = fmaxf(m, fmaxf(fmaxf(v.x, v.y), fmaxf(v.z, v.w)));
        __half2 h01 = __floats2half2_rn(v.x, v.y);
        __half2 h23 = __floats2half2_rn(v.z, v.w);
        uint2 u;
        u.x = *(unsigned*)&h01;
        u.y = *(unsigned*)&h23;
        sh[i] = u;
    }
#pragma unroll
    for (int off = 16; off; off >>= 1) {
        s += __shfl_down_sync(0xffffffffu, s, off);
        m = fmaxf(m, __shfl_down_sync(0xffffffffu, m, off));
    }
    __shared__ float ss[8], sm[8];
    if ((threadIdx.x & 31) == 0) { ss[threadIdx.x >> 5] = s; sm[threadIdx.x >> 5] = m; }
    __syncthreads();
    if (threadIdx.x == 0) {
        float S = 0.f, M = -CUDART_INF_F;
#pragma unroll
        for (int i = 0; i < 8; i++) { S += ss[i]; M = fmaxf(M, sm[i]); }
        g_avg[plane] = S * (1.f / 4096.f);
        g_max[plane] = M;
    }
}

// ---------------------------------------------------------------------------
// k2: channel MLP + sigmoid -> g_catt. 32 blocks x 256 thr.
// ---------------------------------------------------------------------------
__global__ __launch_bounds__(256) void k2_mlp(const float* __restrict__ w1,
                                              const float* __restrict__ w2) {
    int b   = blockIdx.x;
    int tid = threadIdx.x;
    __shared__ float s_avg[C], s_mx[C], s_h[HID];
    dep_sync();                                 // wait for k1 stats
    s_avg[tid] = g_avg[b * C + tid];
    s_mx [tid] = g_max[b * C + tid];
    __syncthreads();

    int r = tid >> 4, l16 = tid & 15;
    float pa = 0.f, pm = 0.f;
#pragma unroll
    for (int j = 0; j < 16; j++) {
        int c = l16 + j * 16;
        float w = w1[r * C + c];
        pa += w * s_avg[c];
        pm += w * s_mx[c];
    }
#pragma unroll
    for (int off = 8; off; off >>= 1) {
        pa += __shfl_down_sync(0xffffffffu, pa, off, 16);
        pm += __shfl_down_sync(0xffffffffu, pm, off, 16);
    }
    if (l16 == 0) s_h[r] = fmaxf(pa, 0.f) + fmaxf(pm, 0.f);
    __syncthreads();

    float acc = 0.f;
#pragma unroll
    for (int rr = 0; rr < HID; rr++) acc += s_h[rr] * w2[tid * HID + rr];
    g_catt[b * C + tid] = sigmoidf(acc);
}

// ---------------------------------------------------------------------------
// k3: spatial mean/max of x16*catt. 1024 blocks x 256 thr.
// catt read directly via __ldg (L2 broadcast) -> no entry smem stage/sync;
// streaming loads start immediately after dep_sync.
// ---------------------------------------------------------------------------
__global__ __launch_bounds__(256) void k3_spstats() {
    const int b   = blockIdx.x >> 5;
    const int g   = blockIdx.x & 31;            // 32 groups of 128 px
    const int tid = threadIdx.x;

    dep_sync();                                 // wait for k2 catt

    const int u4    = tid & 15;
    const int split = tid >> 4;             // 16 channels each
    const uint4* xp = (const uint4*)g_x16 + (size_t)(b * C) * 512 + g * 16 + u4;
    const float* cp = &g_catt[b * C + split * 16];

    float s[8], m[8];
#pragma unroll
    for (int i = 0; i < 8; i++) { s[i] = 0.f; m[i] = -CUDART_INF_F; }

#pragma unroll
    for (int j = 0; j < 16; j++) {
        float a = __ldg(&cp[j]);
        uint4 u = xp[(size_t)(split * 16 + j) * 512];
        float2 f01 = __half22float2(*(__half2*)&u.x);
        float2 f23 = __half22float2(*(__half2*)&u.y);
        float2 f45 = __half22float2(*(__half2*)&u.z);
        float2 f67 = __half22float2(*(__half2*)&u.w);
        float v[8] = {f01.x, f01.y, f23.x, f23.y, f45.x, f45.y, f67.x, f67.y};
#pragma unroll
        for (int i = 0; i < 8; i++) {
            float t = v[i] * a;
            s[i] += t;
            m[i] = fmaxf(m[i], t);
        }
    }

    __shared__ float rsum[16][16][8];
    __shared__ float rmax[16][16][8];
#pragma unroll
    for (int i = 0; i < 8; i++) { rsum[split][u4][i] = s[i]; rmax[split][u4][i] = m[i]; }
    __syncthreads();

    if (tid < 128) {
        int p = tid >> 3, lane = tid & 7;
        float S = rsum[0][p][lane], M = rmax[0][p][lane];
#pragma unroll
        for (int i = 1; i < 16; i++) {
            S += rsum[i][p][lane];
            M = fmaxf(M, rmax[i][p][lane]);
        }
        int pix = g * 128 + p * 8 + lane;
        g_spavg[b * HW + pix] = S * (1.f / (float)C);
        g_spmax[b * HW + pix] = M;
    }
}

// ---------------------------------------------------------------------------
// k4: 7x7 "same" conv + sigmoid -> g_att. 512 blocks x 256 thr, 1 px/thread.
// Weight load + tile zeroing happen BEFORE dep_sync (overlaps k3 tail).
// ---------------------------------------------------------------------------
__global__ __launch_bounds__(256) void k4_conv(const float* __restrict__ w_sp) {
    const int b    = blockIdx.x >> 4;
    const int band = blockIdx.x & 15;
    const int h0   = band * 4;
    const int tid  = threadIdx.x;

    __shared__ float sp[2][10 * 72];            // rows h0-3..h0+6, col pad 3
    __shared__ float s_w[98];

    // pre-sync work: weights (kernel input, not produced by k3) + zero fill
    if (tid < 98) s_w[tid] = w_sp[tid];
    for (int i = tid; i < 2 * 10 * 72; i += 256) ((float*)sp)[i] = 0.f;

    dep_sync();                                 // wait for k3 spavg/spmax
    __syncthreads();

    for (int idx = tid; idx < 10 * 64; idx += 256) {
        int r  = idx >> 6;
        int cx = idx & 63;
        int gh = h0 + r - 3;
        if (gh >= 0 && gh < 64) {
            sp[0][r * 72 + 3 + cx] = g_spavg[b * HW + gh * 64 + cx];
            sp[1][r * 72 + 3 + cx] = g_spmax[b * HW + gh * 64 + cx];
        }
    }
    __syncthreads();

    int hl = tid >> 6;      // 0..3
    int wx = tid & 63;
    float acc = 0.f;
#pragma unroll
    for (int i = 0; i < 2; i++)
#pragma unroll
        for (int kh = 0; kh < 7; kh++) {
            const float* row  = &sp[i][(hl + kh) * 72 + wx];
            const float* wrow = &s_w[i * 49 + kh * 7];
#pragma unroll
            for (int kw = 0; kw < 7; kw++)
                acc += row[kw] * wrow[kw];
        }
    g_att[b * HW + (h0 + hl) * 64 + wx] = sigmoidf(acc);
}

// ---------------------------------------------------------------------------
// k5: pure apply: out = x16 * catt * att. 2048 blocks x 256 thr.
// NO shared memory, NO __syncthreads: att/catt read directly via __ldg
// (L2-broadcast, tiny) so the 8 streaming loads issue immediately.
// ---------------------------------------------------------------------------
__global__ __launch_bounds__(256) void k5_final(float* __restrict__ out) {
    const int b    = blockIdx.x >> 6;
    const int rest = blockIdx.x & 63;
    const int band = rest >> 3;             // 0..7 -> 8 rows each
    const int cg   = rest & 7;              // 0..7 -> 32 channels each
    const int tid  = threadIdx.x;

    dep_sync();                                 // wait for k4 att

    const int u4    = tid & 63;             // 8 consecutive pixels in band
    const int split = tid >> 6;             // 0..3

    const float4* attp = (const float4*)g_att + (size_t)b * 1024 + band * 128 + u4 * 2;
    const float4 aA = __ldg(attp);
    const float4 aB = __ldg(attp + 1);

    const float* cp = &g_catt[b * C + cg * 32 + split * 8];

    const uint4* xbase = (const uint4*)g_x16
                       + (size_t)(b * C + cg * 32) * 512 + band * 64 + u4;
    float4* obase = (float4*)out
                  + ((size_t)(b * C + cg * 32) * 1024) + band * 128 + u4 * 2;

#pragma unroll 4
    for (int j = 0; j < 8; j++) {
        int ci   = split * 8 + j;
        float ca = __ldg(&cp[j]);
        uint4 u  = __ldcs(&xbase[(size_t)ci * 512]);
        float2 f01 = __half22float2(*(__half2*)&u.x);
        float2 f23 = __half22float2(*(__half2*)&u.y);
        float2 f45 = __half22float2(*(__half2*)&u.z);
        float2 f67 = __half22float2(*(__half2*)&u.w);
        float4 oA, oB;
        oA.x = f01.x * ca * aA.x;
        oA.y = f01.y * ca * aA.y;
        oA.z = f23.x * ca * aA.z;
        oA.w = f23.y * ca * aA.w;
        oB.x = f45.x * ca * aB.x;
        oB.y = f45.y * ca * aB.y;
        oB.z = f67.x * ca * aB.z;
        oB.w = f67.y * ca * aB.w;
        __stcs(obase + (size_t)ci * 1024, oA);
        __stcs(obase + (size_t)ci * 1024 + 1, oB);
    }
}

// ---------------------------------------------------------------------------
// host: PDL-chained launches with plain fallback
// ---------------------------------------------------------------------------
template <typename... Args>
static void launch_pdl(void (*kern)(Args...), dim3 grid, dim3 block, Args... args) {
    cudaLaunchConfig_t cfg = {};
    cfg.gridDim  = grid;
    cfg.blockDim = block;
    cfg.stream   = 0;
    cudaLaunchAttribute attr[1];
    attr[0].id = cudaLaunchAttributeProgrammaticStreamSerialization;
    attr[0].val.programmaticStreamSerializationAllowed = 1;
    cfg.attrs    = attr;
    cfg.numAttrs = 1;
    cudaError_t err = cudaLaunchKernelEx(&cfg, kern, args...);
    if (err != cudaSuccess) {
        cudaGetLastError();                     // clear, fall back
        kern<<<grid, block>>>(args...);
    }
}

extern "C" void kernel_launch(void* const* d_in, const int* in_sizes, int n_in,
                              void* d_out, int out_size) {
    const float* x    = (const float*)d_in[0];   // [32,256,64,64]
    const float* w1   = (const float*)d_in[1];   // [16,256]
    const float* w2   = (const float*)d_in[2];   // [256,16]
    const float* w_sp = (const float*)d_in[3];   // [1,2,7,7]
    float* out = (float*)d_out;

    k1_stats_cvt<<<B * C, 256>>>(x);
    launch_pdl(k2_mlp,     dim3(B),       dim3(256), w1, w2);
    launch_pdl(k3_spstats, dim3(B * 32),  dim3(256));
    launch_pdl(k4_conv,    dim3(B * 16),  dim3(256), w_sp);
    launch_pdl(k5_final,   dim3(B * 64),  dim3(256), out);
}